// round 14
// baseline (speedup 1.0000x reference)
#include <cuda_runtime.h>
#include <cuda_bf16.h>
#include <stdint.h>

#define NTOK 4096
#define NEDGE 131072
#define TNUM 8
#define RNUM 16
#define HNUM 8
#define BNUM 21
#define SEEDS 128
#define CAP 96            // per-row edge-list capacity (avg degree = 32, max ~66)

// ---------------------------------------------------------------------------
// Device scratch.
// RULE (learned R5/R9): fill_kernel must NEVER write a __device__ global —
// doing so kills read-only caching of its inputs and halves fill BW.
// g_zero_region = [cursor[NTOK] | overcnt] — wiped by one graph memset node.
// ---------------------------------------------------------------------------
__device__ int g_zero_region[NTOK + 1];   // [0..NTOK) cursors, [NTOK] overcnt
__device__ int g_elist[NTOK * CAP];       // packed (dst << 4) | rel, per row
__device__ int g_over[NEDGE];             // packed (src << 16) | (dst << 4) | rel

#define g_cursor  g_zero_region
#define g_overcnt g_zero_region[NTOK]

// ---------------------------------------------------------------------------
__device__ __forceinline__ int bucketize(float dt) {
    float s  = (dt > 0.0f) ? 1.0f : ((dt < 0.0f) ? -1.0f : 0.0f);
    float sl = s * log1pf(fabsf(dt) + 1e-6f);
    float c  = fminf(fmaxf(sl, -5.0f), 5.0f);
    float norm = (c + 5.0f) / (10.0f + 1e-9f);
    int idx = (int)floorf(norm * (float)(BNUM - 1));
    idx = idx < 0 ? 0 : idx;
    idx = idx > (BNUM - 1) ? (BNUM - 1) : idx;
    return idx;
}

// ---------------------------------------------------------------------------
// One-pass per-row edge-list build (stream-ordered after the memset node).
// ---------------------------------------------------------------------------
__global__ __launch_bounds__(256) void build_kernel(
    const int* __restrict__ edge_src,
    const int* __restrict__ edge_dst,
    const int* __restrict__ edge_rel)
{
    cudaTriggerProgrammaticLaunchCompletion();   // let fill start launching
    const int e = blockIdx.x * blockDim.x + threadIdx.x;
    if (e >= NEDGE) return;
    const int s = edge_src[e];
    const int d = edge_dst[e];
    const int r = edge_rel[e];
    const int pos = atomicAdd(&g_cursor[s], 1);
    if (pos < CAP) {
        g_elist[s * CAP + pos] = (d << 4) | r;
    } else {
        const int o = atomicAdd(&g_overcnt, 1);
        g_over[o] = (s << 16) | (d << 4) | r;
    }
}

// ---------------------------------------------------------------------------
// Fill kernel (PDL over build): ONE BLOCK PER ROW i, all 8 heads.
// token_type is loaded once per row (not once per (row, head)) -> 8x less
// LDG traffic through L1, freeing wavefront slots for the store stream.
//   Phase 1:  per element: 1 int4 load -> 8 gathered float4 stores.
//   Phase 2a: this row's edges x 8 heads via L2-hit atomicAdd.
//   Phase 2b: overflow entries (normally zero).
// ---------------------------------------------------------------------------
__global__ __launch_bounds__(256) void fill_kernel(
    const int*   __restrict__ token_type,
    const float* __restrict__ time_vec,
    const float* __restrict__ typepair_bias,  // (T, T, H)
    const float* __restrict__ temp_bias,      // (B, H)
    const float* __restrict__ adj_rel_bias,   // (R, H)
    float*       __restrict__ out)            // (H, N, N)
{
    const int i = blockIdx.x;
    const int tid = threadIdx.x;

    __shared__ float vals[HNUM][TNUM];   // vals[h][t] = typepair_bias[tt_i][t][h]
    __shared__ float tb[BNUM][HNUM];     // tb[b][h]
    __shared__ float relb[RNUM][HNUM];   // relb[r][h]

    // init LUTs (all tiny, L2-hot)
    if (tid < HNUM * TNUM) {
        const int h = tid >> 3, t = tid & 7;
        const int tt_i = token_type[i];
        vals[h][t] = typepair_bias[(tt_i * TNUM + t) * HNUM + h];
    }
    if (tid >= 64 && tid < 64 + BNUM * HNUM) {
        const int k = tid - 64;
        tb[k >> 3][k & 7] = temp_bias[k];
    }
    if (tid >= 232 && tid < 232 + RNUM * HNUM / 8) {  // 16 threads x 8 scalars
        const int k = (tid - 232) * 8;
        #pragma unroll
        for (int q = 0; q < 8; q++)
            relb[(k + q) >> 3][(k + q) & 7] = adj_rel_bias[k + q];
    }
    __syncthreads();

    const bool  is_seed = (i < SEEDS);
    const float ti      = is_seed ? time_vec[i] : 0.0f;

    float* __restrict__ orow0 = out + (size_t)i * NTOK;   // h stride = NTOK*NTOK

    // Phase 1: each thread handles 4 j-elements x 8 heads
    #pragma unroll
    for (int j0 = tid * 4; j0 < NTOK; j0 += 256 * 4) {
        const int4 t4 = *reinterpret_cast<const int4*>(token_type + j0);
        int b0 = 0, b1 = 0, b2 = 0, b3 = 0;
        if (is_seed) {
            const float4 tv = *reinterpret_cast<const float4*>(time_vec + j0);
            b0 = bucketize(tv.x - ti);
            b1 = bucketize(tv.y - ti);
            b2 = bucketize(tv.z - ti);
            b3 = bucketize(tv.w - ti);
        }
        #pragma unroll
        for (int h = 0; h < HNUM; h++) {
            float4 v;
            v.x = vals[h][t4.x];
            v.y = vals[h][t4.y];
            v.z = vals[h][t4.z];
            v.w = vals[h][t4.w];
            if (is_seed) {
                v.x += tb[b0][h];
                v.y += tb[b1][h];
                v.z += tb[b2][h];
                v.w += tb[b3][h];
            }
            *reinterpret_cast<float4*>(orow0 + (size_t)h * NTOK * NTOK + j0) = v;
        }
    }
    __syncthreads();               // all 8 row-planes stored before RMW

    cudaGridDependencySynchronize();   // build's cursors/lists now visible

    // Phase 2a: this row's edges x 8 heads — L2-hit atomics
    const int count = min(g_cursor[i], CAP);
    for (int idx = tid; idx < count * HNUM; idx += 256) {
        const int e = idx >> 3;
        const int h = idx & 7;
        const int p = g_elist[i * CAP + e];
        atomicAdd(orow0 + (size_t)h * NTOK * NTOK + (p >> 4), relb[p & 15][h]);
    }

    // Phase 2b: overflow entries for this row (normally g_overcnt == 0)
    const int on = g_overcnt;
    for (int idx = tid; idx < on * HNUM; idx += 256) {
        const int e = idx >> 3;
        const int h = idx & 7;
        const int p = g_over[e];
        if ((p >> 16) == i)
            atomicAdd(orow0 + (size_t)h * NTOK * NTOK + ((p >> 4) & 0xFFF),
                      relb[p & 15][h]);
    }
}

// ---------------------------------------------------------------------------
// Launch: memset (graph node) -> build -> (PDL) -> fill.
// ---------------------------------------------------------------------------
extern "C" void kernel_launch(void* const* d_in, const int* in_sizes, int n_in,
                              void* d_out, int out_size)
{
    const int*   token_type    = (const int*)  d_in[0];
    const int*   edge_src      = (const int*)  d_in[1];
    const int*   edge_dst      = (const int*)  d_in[2];
    const int*   edge_rel      = (const int*)  d_in[3];
    const float* time_vec      = (const float*)d_in[4];
    const float* adj_rel_bias  = (const float*)d_in[n_in - 3];
    const float* typepair_bias = (const float*)d_in[n_in - 2];
    const float* temp_bias     = (const float*)d_in[n_in - 1];
    float* out = (float*)d_out;

    // Zero cursors + overcnt via a graph memset node
    void* zr = nullptr;
    cudaGetSymbolAddress(&zr, g_zero_region);
    cudaMemsetAsync(zr, 0, (NTOK + 1) * sizeof(int), 0);

    // build: stream-ordered after the memset
    build_kernel<<<(NEDGE + 255) / 256, 256>>>(edge_src, edge_dst, edge_rel);

    // fill: PDL over build, one block per row
    cudaLaunchAttribute pdl[1];
    pdl[0].id = cudaLaunchAttributeProgrammaticStreamSerialization;
    pdl[0].val.programmaticStreamSerializationAllowed = 1;

    cudaLaunchConfig_t cfg = {};
    cfg.gridDim  = dim3(NTOK);
    cfg.blockDim = dim3(256);
    cfg.attrs    = pdl;
    cfg.numAttrs = 1;
    cfg.stream   = 0;
    cudaLaunchKernelEx(&cfg, fill_kernel, token_type, time_vec,
                       typepair_bias, temp_bias, adj_rel_bias, out);
}